// round 11
// baseline (speedup 1.0000x reference)
#include <cuda_runtime.h>
#include <cuda_fp16.h>
#include <cstdint>

// Problem constants
#define BB 32
#define NN 1024
#define IN_DIM 64
#define HID 128
#define OUTD 64        // 2*LAT
#define NUM_LAYERS 3

// fp16 range management (all powers of two => exact):
//   hT buffers store h * SH  (SH = 1/16)
//   Tbuf stores T_true * SH * ST2 = T_true/1024  (ST2 = 1/64)
//   epilogue: h' = relu(acc2 * 1024 + rowsum*bl)
#define SH_F    0.0625f      // 2^-4
#define ST2_F   0.015625f    // 2^-6
#define UNSC_F  1024.0f      // 1/(SH*ST2)

// Scratch (device globals; no allocations allowed)
__device__ __half g_adjh[(size_t)BB * NN * NN];       // 67 MB fp16 adjacency
__device__ __half g_hT[2][(size_t)BB * HID * NN];     // ping-pong transposed activations (scaled by SH)
__device__ float  g_h[(size_t)BB * NN * HID];         // layer-2 normal-layout output (unscaled)
__device__ float  g_rowsum[BB * NN];                  // per-node adjacency row sums
__device__ __half g_WlTh[NUM_LAYERS * HID * HID];     // Wl transposed, fp16

// ============================================================================
// Helpers
// ============================================================================
__device__ __forceinline__ uint32_t smem_u32(const void* p) {
    uint32_t a;
    asm("{ .reg .u64 t; cvta.to.shared.u64 t, %1; cvt.u32.u64 %0, t; }"
        : "=r"(a) : "l"(p));
    return a;
}

__device__ __forceinline__ uint32_t pack_h2(float a, float b) {
    __half2 h = __floats2half2_rn(a, b);
    return *reinterpret_cast<uint32_t*>(&h);
}

__device__ __forceinline__ void mma_f16(float c[4],
                                        uint32_t a0, uint32_t a1, uint32_t a2, uint32_t a3,
                                        uint32_t b0, uint32_t b1) {
    asm volatile(
        "mma.sync.aligned.m16n8k16.row.col.f32.f16.f16.f32 "
        "{%0,%1,%2,%3}, {%4,%5,%6,%7}, {%8,%9}, {%0,%1,%2,%3};"
        : "+f"(c[0]), "+f"(c[1]), "+f"(c[2]), "+f"(c[3])
        : "r"(a0), "r"(a1), "r"(a2), "r"(a3), "r"(b0), "r"(b1));
}

#define LDMX4(r0, r1, r2, r3, addr) \
    asm volatile("ldmatrix.sync.aligned.m8n8.x4.shared.b16 {%0,%1,%2,%3}, [%4];" \
                 : "=r"(r0), "=r"(r1), "=r"(r2), "=r"(r3) : "r"(addr))

#define CP_ASYNC16(dst, src) \
    asm volatile("cp.async.cg.shared.global [%0], [%1], 16;" :: "r"(dst), "l"(src))
#define CP_COMMIT() asm volatile("cp.async.commit_group;" ::: "memory")
#define CP_WAIT1()  asm volatile("cp.async.wait_group 1;" ::: "memory")
#define CP_WAIT0()  asm volatile("cp.async.wait_group 0;" ::: "memory")

// Load one 16KB fp16 tile (128 rows x 64 halves, 128B rows) via cp.async.
// 16B word q of row r stored at word q ^ (r&7): conflict-free fill + ldmatrix.
__device__ __forceinline__ void load_tile16(
    uint32_t dst, const __half* __restrict__ src, int rowstride_h, int tid)
{
#pragma unroll
    for (int i = 0; i < 4; i++) {
        int idx = tid + i * 256;             // 0..1023
        int row = idx >> 3;                  // 0..127
        int q   = idx & 7;                   // 16B word
        CP_ASYNC16(dst + row * 128 + ((q ^ (row & 7)) << 4),
                   src + (size_t)row * rowstride_h + q * 8);
    }
}

// ============================================================================
// Prep kernels
// ============================================================================
__global__ void prep_wlt(const float* __restrict__ Wl, __half* __restrict__ wlt) {
    int l = blockIdx.x;
    const float* W = Wl + (size_t)l * HID * HID;
    __half* T = wlt + (size_t)l * HID * HID;
    for (int i = threadIdx.x; i < HID * HID; i += blockDim.x) {
        int n2 = i >> 7, n = i & 127;
        T[i] = __float2half(W[n * HID + n2]);
    }
}

// adj fp32 -> fp16 copy + per-row sums. One warp per adjacency row.
__global__ __launch_bounds__(256) void conv_rowsum(
    const float* __restrict__ adj, __half* __restrict__ adjh, float* __restrict__ rs)
{
    int warp = (blockIdx.x * blockDim.x + threadIdx.x) >> 5;   // row id
    int lane = threadIdx.x & 31;
    const float* src = adj + (size_t)warp * NN;
    __half* dst = adjh + (size_t)warp * NN;
    float s = 0.f;
#pragma unroll
    for (int i = 0; i < 8; i++) {
        float4 v = *reinterpret_cast<const float4*>(src + i * 128 + lane * 4);
        s += v.x + v.y + v.z + v.w;
        union { __half2 h[2]; uint2 u; } pk;
        pk.h[0] = __floats2half2_rn(v.x, v.y);
        pk.h[1] = __floats2half2_rn(v.z, v.w);
        *reinterpret_cast<uint2*>(dst + i * 128 + lane * 4) = pk.u;
    }
#pragma unroll
    for (int off = 16; off; off >>= 1) s += __shfl_xor_sync(0xFFFFFFFFu, s, off);
    if (lane == 0) rs[warp] = s;
}

// ============================================================================
// Register-tiled side GEMM (SIMT fp32): C = (A[M,K] @ W[K,BN] + bias) (*mask),
// optional transposed output (fp16 hT, scaled by SH, for TRANS+HALFOUT).
// ============================================================================
template<int K, int BN, bool BIAS, bool MASK, bool TRANS, bool HALFOUT>
__global__ __launch_bounds__(256) void tile_gemm(
    const float* __restrict__ A, const float* __restrict__ W,
    const float* __restrict__ bias, const float* __restrict__ mask,
    void* __restrict__ Cv)
{
    constexpr int BM = 128, BK = 16;
    constexpr int VN = BN / 16;
    __shared__ float As[BK][BM + 4];
    __shared__ float Bs[BK][BN];

    const int tid  = threadIdx.x;
    const int tx   = tid & 15;
    const int ty   = tid >> 4;
    const int row0 = blockIdx.x * BM;
    const int col0 = tx * VN;

    float acc[8][VN];
#pragma unroll
    for (int i = 0; i < 8; i++)
#pragma unroll
        for (int j = 0; j < VN; j++) acc[i][j] = 0.f;

    for (int k0 = 0; k0 < K; k0 += BK) {
#pragma unroll
        for (int i = 0; i < 2; i++) {
            int f = tid + i * 256;
            int m = f >> 2, kq = f & 3;
            float4 v = *reinterpret_cast<const float4*>(
                &A[(size_t)(row0 + m) * K + k0 + kq * 4]);
            As[kq * 4 + 0][m] = v.x;
            As[kq * 4 + 1][m] = v.y;
            As[kq * 4 + 2][m] = v.z;
            As[kq * 4 + 3][m] = v.w;
        }
#pragma unroll
        for (int i = 0; i < (BK * BN) / (4 * 256); i++) {
            int f  = tid + i * 256;
            int kk = f / (BN / 4);
            int nq = f % (BN / 4);
            *reinterpret_cast<float4*>(&Bs[kk][nq * 4]) =
                *reinterpret_cast<const float4*>(&W[(size_t)(k0 + kk) * BN + nq * 4]);
        }
        __syncthreads();
#pragma unroll
        for (int k = 0; k < BK; k++) {
            float ra[8], rb[VN];
#pragma unroll
            for (int i = 0; i < 8; i++)  ra[i] = As[k][ty * 8 + i];
#pragma unroll
            for (int j = 0; j < VN; j++) rb[j] = Bs[k][col0 + j];
#pragma unroll
            for (int i = 0; i < 8; i++)
#pragma unroll
                for (int j = 0; j < VN; j++)
                    acc[i][j] += ra[i] * rb[j];
        }
        __syncthreads();
    }

    float bv[VN];
#pragma unroll
    for (int j = 0; j < VN; j++) bv[j] = BIAS ? bias[col0 + j] : 0.f;

    if (TRANS) {
        const int bb    = row0 >> 10;
        const int node0 = (row0 & (NN - 1)) + ty * 8;
#pragma unroll
        for (int j = 0; j < VN; j++) {
            if (HALFOUT) {
                __half* dst = (__half*)Cv + ((size_t)(bb * HID + col0 + j)) * NN + node0;
                union { __half2 h[4]; uint4 u; } pk;
#pragma unroll
                for (int i = 0; i < 4; i++)
                    pk.h[i] = __floats2half2_rn((acc[2 * i][j] + bv[j]) * SH_F,
                                                (acc[2 * i + 1][j] + bv[j]) * SH_F);
                *reinterpret_cast<uint4*>(dst) = pk.u;
            } else {
                float* dst = (float*)Cv + ((size_t)(bb * HID + col0 + j)) * NN + node0;
#pragma unroll
                for (int i = 0; i < 8; i += 4) {
                    float4 v;
                    v.x = acc[i + 0][j] + bv[j];
                    v.y = acc[i + 1][j] + bv[j];
                    v.z = acc[i + 2][j] + bv[j];
                    v.w = acc[i + 3][j] + bv[j];
                    *reinterpret_cast<float4*>(&dst[i]) = v;
                }
            }
        }
    } else {
        float* C = (float*)Cv;
#pragma unroll
        for (int i = 0; i < 8; i++) {
            int row = row0 + ty * 8 + i;
            float m = MASK ? mask[row] : 1.f;
#pragma unroll
            for (int j = 0; j < VN; j += 4) {
                float4 v;
                v.x = (acc[i][j + 0] + bv[j + 0]) * m;
                v.y = (acc[i][j + 1] + bv[j + 1]) * m;
                v.z = (acc[i][j + 2] + bv[j + 2]) * m;
                v.w = (acc[i][j + 3] + bv[j + 3]) * m;
                *reinterpret_cast<float4*>(&C[(size_t)row * BN + col0 + j]) = v;
            }
        }
    }
}

// ============================================================================
// Fused GCN layer (fp16 tensor cores, ldmatrix + register double-buffering):
//   acc = adjh[b] @ (h_in*SH)^T ; Tbuf = acc/64 ; h' = relu(1024*(Tbuf@Wl)+rs*bl)
// 8 warps, warp tile 64x32. 3-stage cp.async ring, single barrier per iter.
// B frags double-buffered across kk; A frags double-buffered across mt.
// ============================================================================
#define ST 3
#define BKH 64                     // K per chunk (64 halves = 128B row)
#define NITH (NN / BKH)            // 16
#define TILE16 16384
#define HBUF_OFF (4 * TILE16)      // h'buf overlaps slots 4,5 (epilogue only)
#define HBUF_STRIDE 136            // halves per feat row (272B, 16B-aligned)
#define SMTOT (HBUF_OFF + 128 * HBUF_STRIDE * 2)   // 100352 B

template<bool LAST>
__global__ __launch_bounds__(256, 2) void adj_layer(
    const __half* __restrict__ adjh, const __half* __restrict__ hTin,
    const __half* __restrict__ wlt,  const float* __restrict__ bl,
    const float* __restrict__ rowsum,
    __half* __restrict__ hTout, float* __restrict__ hnorm)
{
    extern __shared__ __align__(1024) char smem[];
    const uint32_t sb = smem_u32(smem);
    const int tid = threadIdx.x;
    const int wid = tid >> 5;
    const int lid = tid & 31;
    const int g   = lid >> 2;
    const int tg  = lid & 3;

    const int m_warp = (wid & 1) * 64;
    const int n_warp = (wid >> 1) * 32;

    const int b    = blockIdx.y;
    const int row0 = blockIdx.x * 128;

    const __half* Ab = adjh + (size_t)b * NN * NN + (size_t)row0 * NN;
    const __half* Bb = hTin + (size_t)b * HID * NN;

    // ---- ldmatrix lane-address precompute (addr = Q ^ (kk<<5), Q invariant) ----
    const int xr  = lid & 7;
    const int rAo = ((lid >> 3) & 1) * 8;
    const int w0A = (lid >> 4) & 1;
    uint32_t Qa[4];
#pragma unroll
    for (int mt = 0; mt < 4; mt++) {
        int r = m_warp + mt * 16 + rAo + xr;
        Qa[mt] = (uint32_t)(r * 128 + ((w0A ^ xr) << 4));
    }
    const int w0B = (lid >> 3) & 1;
    const int ntB = (lid >> 4) & 1;
    uint32_t Qb[2];
#pragma unroll
    for (int p = 0; p < 2; p++) {
        int rn = n_warp + (p * 2 + ntB) * 8 + xr;
        Qb[p] = (uint32_t)(rn * 128 + ((w0B ^ xr) << 4));
    }

    float acc[4][4][4];
#pragma unroll
    for (int mt = 0; mt < 4; mt++)
#pragma unroll
        for (int nt = 0; nt < 4; nt++)
#pragma unroll
            for (int r = 0; r < 4; r++) acc[mt][nt][r] = 0.f;

    // ---- mainloop. Preload chunks 0,1 (group == chunk via per-chunk commit). ----
#pragma unroll
    for (int p = 0; p < 2; p++) {
        load_tile16(sb + p * TILE16, Ab + p * BKH, NN, tid);
        load_tile16(sb + (ST + p) * TILE16, Bb + p * BKH, NN, tid);
        CP_COMMIT();
    }

    for (int it = 0; it < NITH; it++) {
        const int s = it % ST;
        CP_WAIT1();                 // chunk 'it' arrived
        __syncthreads();            // all warps done with MMA(it-1)

        const uint32_t sA = sb + s * TILE16;
        const uint32_t sB = sb + (ST + s) * TILE16;

        // Register pipeline: bf[kk&1], af[mt&1]
        uint32_t bf[2][4][2];
        uint32_t af[2][4];
        LDMX4(bf[0][0][0], bf[0][0][1], bf[0][1][0], bf[0][1][1], sB + Qb[0]);
        LDMX4(bf[0][2][0], bf[0][2][1], bf[0][3][0], bf[0][3][1], sB + Qb[1]);
        LDMX4(af[0][0], af[0][1], af[0][2], af[0][3], sA + Qa[0]);

#pragma unroll
        for (int kk = 0; kk < 4; kk++) {
            const uint32_t kx  = (uint32_t)kk << 5;
            const uint32_t kxn = (uint32_t)(kk + 1) << 5;
            const int cb = kk & 1, nb = cb ^ 1;
            if (kk < 3) {           // prefetch next kk's B frags
                LDMX4(bf[nb][0][0], bf[nb][0][1], bf[nb][1][0], bf[nb][1][1],
                      (sB + Qb[0]) ^ kxn);
                LDMX4(bf[nb][2][0], bf[nb][2][1], bf[nb][3][0], bf[nb][3][1],
                      (sB + Qb[1]) ^ kxn);
            }
#pragma unroll
            for (int mt = 0; mt < 4; mt++) {
                const int ca = mt & 1, na = ca ^ 1;
                if (mt < 3) {       // prefetch next mt's A frags (same kk)
                    LDMX4(af[na][0], af[na][1], af[na][2], af[na][3],
                          (sA + Qa[mt + 1]) ^ kx);
                } else if (kk < 3) {// prefetch mt=0 of next kk
                    LDMX4(af[na][0], af[na][1], af[na][2], af[na][3],
                          (sA + Qa[0]) ^ kxn);
                }
#pragma unroll
                for (int nt = 0; nt < 4; nt++)
                    mma_f16(acc[mt][nt], af[ca][0], af[ca][1], af[ca][2], af[ca][3],
                            bf[cb][nt][0], bf[cb][nt][1]);
            }
            if (kk == 0) {          // issue next-next chunk's loads off the LDSM burst
                if (it + 2 < NITH) {
                    const int sl = (it + 2) % ST;
                    load_tile16(sb + sl * TILE16, Ab + (it + 2) * BKH, NN, tid);
                    load_tile16(sb + (ST + sl) * TILE16, Bb + (it + 2) * BKH, NN, tid);
                }
                CP_COMMIT();        // unconditional: keeps group==chunk alignment
            }
        }
    }

    // ---- epilogue: h' = relu(1024*(Tbuf @ Wl) + rowsum*bl) ----
    // WlT ch0 -> slot 2 (A stage 2: idle since iter 14)
    load_tile16(sb + 2 * TILE16, wlt, HID, tid);
    CP_COMMIT();

    __syncthreads();                // all MMA(15) reads of slots 0/3 complete

    // WlT ch1 -> slot 3 (B stage 0: safe after the barrier above)
    load_tile16(sb + 3 * TILE16, wlt + 64, HID, tid);
    CP_COMMIT();

    // Tbuf = acc * ST2 (fp32 -> fp16) into slots 0 (cols 0-63) / 1 (64-127)
    {
        char* tb = smem + (n_warp >> 6) * TILE16;
        const int lpb = (n_warp & 63) >> 1;
#pragma unroll
        for (int mt = 0; mt < 4; mt++) {
            int mr = m_warp + mt * 16 + g;
#pragma unroll
            for (int nt = 0; nt < 4; nt++) {
                int lp = lpb + nt * 4 + tg;
                int w = lp >> 2, inner = (lp & 3) * 4;
                *reinterpret_cast<uint32_t*>(
                    tb + mr * 128 + (((w ^ (mr & 7))) << 4) + inner) =
                    pack_h2(acc[mt][nt][0] * ST2_F, acc[mt][nt][1] * ST2_F);
                *reinterpret_cast<uint32_t*>(
                    tb + (mr + 8) * 128 + (((w ^ ((mr + 8) & 7))) << 4) + inner) =
                    pack_h2(acc[mt][nt][2] * ST2_F, acc[mt][nt][3] * ST2_F);
            }
        }
    }
    CP_WAIT0();
    __syncthreads();

    float acc2[4][4][4];
#pragma unroll
    for (int mt = 0; mt < 4; mt++)
#pragma unroll
        for (int nt = 0; nt < 4; nt++)
#pragma unroll
            for (int r = 0; r < 4; r++) acc2[mt][nt][r] = 0.f;

#pragma unroll
    for (int ch = 0; ch < 2; ch++) {
        const uint32_t sT = sb + ch * TILE16;            // Tbuf
        const uint32_t sW = sb + (2 + ch) * TILE16;      // WlT
#pragma unroll
        for (int kk = 0; kk < 4; kk++) {
            const uint32_t kx = (uint32_t)kk << 5;
            uint32_t bf2[4][2];
            LDMX4(bf2[0][0], bf2[0][1], bf2[1][0], bf2[1][1], (sW + Qb[0]) ^ kx);
            LDMX4(bf2[2][0], bf2[2][1], bf2[3][0], bf2[3][1], (sW + Qb[1]) ^ kx);
#pragma unroll
            for (int mt = 0; mt < 4; mt++) {
                uint32_t a0, a1, a2, a3;
                LDMX4(a0, a1, a2, a3, (sT + Qa[mt]) ^ kx);
#pragma unroll
                for (int nt = 0; nt < 4; nt++)
                    mma_f16(acc2[mt][nt], a0, a1, a2, a3, bf2[nt][0], bf2[nt][1]);
            }
        }
    }

    // bias (rowsum * bl) + relu + store
    const float* rsb = rowsum + b * NN + row0;
    float rlo[4], rhi[4];
#pragma unroll
    for (int mt = 0; mt < 4; mt++) {
        rlo[mt] = rsb[m_warp + mt * 16 + g];
        rhi[mt] = rsb[m_warp + mt * 16 + g + 8];
    }
    float b0v[4], b1v[4];
#pragma unroll
    for (int nt = 0; nt < 4; nt++) {
        int col = n_warp + nt * 8 + 2 * tg;
        b0v[nt] = bl[col];
        b1v[nt] = bl[col + 1];
    }

    __half* hb = reinterpret_cast<__half*>(smem + HBUF_OFF);

#pragma unroll
    for (int mt = 0; mt < 4; mt++) {
        int mr = m_warp + mt * 16 + g;
#pragma unroll
        for (int nt = 0; nt < 4; nt++) {
            int col = n_warp + nt * 8 + 2 * tg;
            float v00 = fmaxf(fmaf(acc2[mt][nt][0], UNSC_F, rlo[mt] * b0v[nt]), 0.f);
            float v01 = fmaxf(fmaf(acc2[mt][nt][1], UNSC_F, rlo[mt] * b1v[nt]), 0.f);
            float v10 = fmaxf(fmaf(acc2[mt][nt][2], UNSC_F, rhi[mt] * b0v[nt]), 0.f);
            float v11 = fmaxf(fmaf(acc2[mt][nt][3], UNSC_F, rhi[mt] * b1v[nt]), 0.f);
            if (LAST) {
                float2 p0 = make_float2(v00, v01);
                float2 p1 = make_float2(v10, v11);
                *reinterpret_cast<float2*>(
                    &hnorm[(size_t)(b * NN + row0 + mr) * HID + col]) = p0;
                *reinterpret_cast<float2*>(
                    &hnorm[(size_t)(b * NN + row0 + mr + 8) * HID + col]) = p1;
            } else {
                hb[(col)     * HBUF_STRIDE + mr]     = __float2half(v00 * SH_F);
                hb[(col + 1) * HBUF_STRIDE + mr]     = __float2half(v01 * SH_F);
                hb[(col)     * HBUF_STRIDE + mr + 8] = __float2half(v10 * SH_F);
                hb[(col + 1) * HBUF_STRIDE + mr + 8] = __float2half(v11 * SH_F);
            }
        }
    }

    if (!LAST) {
        __syncthreads();
        // coalesced h'T store: feat row c -> hTout[b][c][row0 .. row0+127]
#pragma unroll
        for (int p = 0; p < 8; p++) {
            int idx = tid + p * 256;
            int c = idx >> 4, u = idx & 15;
            uint4 v = *reinterpret_cast<const uint4*>(hb + c * HBUF_STRIDE + u * 8);
            *reinterpret_cast<uint4*>(
                hTout + ((size_t)(b * HID + c)) * NN + row0 + u * 8) = v;
        }
    }
}

// ============================================================================
// Launch
// Inputs: 0 node_features [B,N,64] | 1 adjacency [B,N,N] | 2 node_mask [B,N,1]
//         3 W_embed [64,128] | 4 Wl [3,128,128] | 5 bl [3,128]
//         6 W_proj [128,64]  | 7 b_proj [64]      Output: [B,N,64] f32
// ============================================================================
extern "C" void kernel_launch(void* const* d_in, const int* in_sizes, int n_in,
                              void* d_out, int out_size)
{
    const float* x     = (const float*)d_in[0];
    const float* adj   = (const float*)d_in[1];
    const float* mask  = (const float*)d_in[2];
    const float* Wemb  = (const float*)d_in[3];
    const float* Wl    = (const float*)d_in[4];
    const float* bl    = (const float*)d_in[5];
    const float* Wproj = (const float*)d_in[6];
    const float* bproj = (const float*)d_in[7];
    float* out = (float*)d_out;

    __half *adjh = nullptr, *hT = nullptr, *wlt = nullptr;
    float *h_ptr = nullptr, *rs = nullptr;
    cudaGetSymbolAddress((void**)&adjh, g_adjh);
    cudaGetSymbolAddress((void**)&hT,   g_hT);
    cudaGetSymbolAddress((void**)&wlt,  g_WlTh);
    cudaGetSymbolAddress((void**)&h_ptr, g_h);
    cudaGetSymbolAddress((void**)&rs,    g_rowsum);
    __half* hT0 = hT;
    __half* hT1 = hT + (size_t)BB * HID * NN;

    cudaFuncSetAttribute(adj_layer<false>,
                         cudaFuncAttributeMaxDynamicSharedMemorySize, SMTOT);
    cudaFuncSetAttribute(adj_layer<true>,
                         cudaFuncAttributeMaxDynamicSharedMemorySize, SMTOT);

    // prep: WlT fp16; adj fp16 + rowsum; embed hT0 = (x @ Wemb)^T * SH, fp16
    prep_wlt<<<NUM_LAYERS, 256>>>(Wl, wlt);
    tile_gemm<IN_DIM, HID, false, false, true, true><<<BB * NN / 128, 256>>>(
        x, Wemb, nullptr, nullptr, hT0);
    conv_rowsum<<<BB * NN / 8, 256>>>(adj, adjh, rs);

    dim3 bigg(NN / 128, BB);   // (8, 32)
    adj_layer<false><<<bigg, 256, SMTOT>>>(adjh, hT0, wlt,                 bl,
                                           rs, hT1, nullptr);
    adj_layer<false><<<bigg, 256, SMTOT>>>(adjh, hT1, wlt + HID * HID,     bl + HID,
                                           rs, hT0, nullptr);
    adj_layer<true ><<<bigg, 256, SMTOT>>>(adjh, hT0, wlt + 2 * HID * HID, bl + 2 * HID,
                                           rs, nullptr, h_ptr);

    // projection + mask (SIMT fp32)
    tile_gemm<HID, OUTD, true, true, false, false><<<BB * NN / 128, 256>>>(
        h_ptr, Wproj, bproj, mask, out);
}

// round 13
// speedup vs baseline: 1.1455x; 1.1455x over previous
#include <cuda_runtime.h>
#include <cuda_fp16.h>
#include <cstdint>

// Problem constants
#define BB 32
#define NN 1024
#define IN_DIM 64
#define HID 128
#define OUTD 64        // 2*LAT
#define NUM_LAYERS 3

// fp16 range management (all powers of two => exact):
//   hT buffers store h * SH  (SH = 1/16)
//   Tbuf stores T_true * SH * ST2 = T_true/1024  (ST2 = 1/64)
//   h3 (proj input) stores h3 * SP (SP = 2^-14: h3 can reach ~1e6; /16 overflowed fp16 in R12)
#define SH_F    0.0625f           // 2^-4
#define ST2_F   0.015625f         // 2^-6
#define UNSC_F  1024.0f           // 1/(SH*ST2)
#define SP_F    6.103515625e-05f  // 2^-14
#define UNSC2_F 16384.0f          // 1/SP

// Scratch (device globals; no allocations allowed)
__device__ __half g_adjh[(size_t)BB * NN * NN];       // 67 MB fp16 adjacency
__device__ __half g_hT[2][(size_t)BB * HID * NN];     // ping-pong transposed activations (scaled SH)
__device__ __half g_xh[(size_t)BB * NN * IN_DIM];     // fp16 node features
__device__ float  g_rowsum[BB * NN];                  // per-node adjacency row sums
__device__ __half g_WlTh[NUM_LAYERS * HID * HID];     // Wl transposed, fp16
__device__ __half g_WembTh[HID * IN_DIM];             // Wemb transposed, fp16
__device__ __half g_WprojTh[2 * OUTD * 64];           // WprojT in 2 k-chunks, fp16

// ============================================================================
// Helpers
// ============================================================================
__device__ __forceinline__ uint32_t smem_u32(const void* p) {
    uint32_t a;
    asm("{ .reg .u64 t; cvta.to.shared.u64 t, %1; cvt.u32.u64 %0, t; }"
        : "=r"(a) : "l"(p));
    return a;
}

__device__ __forceinline__ uint32_t pack_h2(float a, float b) {
    __half2 h = __floats2half2_rn(a, b);
    return *reinterpret_cast<uint32_t*>(&h);
}

__device__ __forceinline__ void mma_f16(float c[4],
                                        uint32_t a0, uint32_t a1, uint32_t a2, uint32_t a3,
                                        uint32_t b0, uint32_t b1) {
    asm volatile(
        "mma.sync.aligned.m16n8k16.row.col.f32.f16.f16.f32 "
        "{%0,%1,%2,%3}, {%4,%5,%6,%7}, {%8,%9}, {%0,%1,%2,%3};"
        : "+f"(c[0]), "+f"(c[1]), "+f"(c[2]), "+f"(c[3])
        : "r"(a0), "r"(a1), "r"(a2), "r"(a3), "r"(b0), "r"(b1));
}

#define LDMX4(r0, r1, r2, r3, addr) \
    asm volatile("ldmatrix.sync.aligned.m8n8.x4.shared.b16 {%0,%1,%2,%3}, [%4];" \
                 : "=r"(r0), "=r"(r1), "=r"(r2), "=r"(r3) : "r"(addr))

#define CP_ASYNC16(dst, src) \
    asm volatile("cp.async.cg.shared.global [%0], [%1], 16;" :: "r"(dst), "l"(src))
#define CP_COMMIT() asm volatile("cp.async.commit_group;" ::: "memory")
#define CP_WAIT1()  asm volatile("cp.async.wait_group 1;" ::: "memory")
#define CP_WAIT0()  asm volatile("cp.async.wait_group 0;" ::: "memory")

// Load one 16KB fp16 tile (128 rows x 64 halves, 128B rows) via cp.async.
// 16B word q of row r stored at word q ^ (r&7): conflict-free fill + ldmatrix.
__device__ __forceinline__ void load_tile16(
    uint32_t dst, const __half* __restrict__ src, int rowstride_h, int tid)
{
#pragma unroll
    for (int i = 0; i < 4; i++) {
        int idx = tid + i * 256;             // 0..1023
        int row = idx >> 3;                  // 0..127
        int q   = idx & 7;                   // 16B word
        CP_ASYNC16(dst + row * 128 + ((q ^ (row & 7)) << 4),
                   src + (size_t)row * rowstride_h + q * 8);
    }
}

// 64-row variant (8KB tile, 64 rows x 64 halves)
__device__ __forceinline__ void load_tile8(
    uint32_t dst, const __half* __restrict__ src, int rowstride_h, int tid)
{
#pragma unroll
    for (int i = 0; i < 2; i++) {
        int idx = tid + i * 256;             // 0..511
        int row = idx >> 3;                  // 0..63
        int q   = idx & 7;
        CP_ASYNC16(dst + row * 128 + ((q ^ (row & 7)) << 4),
                   src + (size_t)row * rowstride_h + q * 8);
    }
}

// ============================================================================
// Prep kernels
// ============================================================================
// bid 0..2: WlT[l]; bid 3: WembT; bid 4: WprojT (2 k-chunks)
__global__ void prep_weights(const float* __restrict__ Wl,
                             const float* __restrict__ Wemb,
                             const float* __restrict__ Wproj,
                             __half* __restrict__ wlt,
                             __half* __restrict__ wembT,
                             __half* __restrict__ wpT)
{
    int bid = blockIdx.x;
    if (bid < NUM_LAYERS) {
        const float* W = Wl + (size_t)bid * HID * HID;
        __half* T = wlt + (size_t)bid * HID * HID;
        for (int i = threadIdx.x; i < HID * HID; i += blockDim.x) {
            int n2 = i >> 7, n = i & 127;
            T[i] = __float2half(W[n * HID + n2]);
        }
    } else if (bid == NUM_LAYERS) {
        // WembT[o][i2] = Wemb[i2][o], o<128, i2<64
        for (int i = threadIdx.x; i < HID * IN_DIM; i += blockDim.x) {
            int o = i >> 6, i2 = i & 63;
            wembT[i] = __float2half(Wemb[i2 * HID + o]);
        }
    } else {
        // wpT[c][o][f'] = Wproj[64c+f'][o], c<2, o<64, f'<64
        for (int i = threadIdx.x; i < 2 * OUTD * 64; i += blockDim.x) {
            int c = i >> 12, o = (i >> 6) & 63, f = i & 63;
            wpT[i] = __float2half(Wproj[(64 * c + f) * OUTD + o]);
        }
    }
}

// x fp32 -> fp16 (streaming)
__global__ __launch_bounds__(256) void conv_x(
    const float* __restrict__ x, __half* __restrict__ xh)
{
    int idx = blockIdx.x * 256 + threadIdx.x;   // one float4 each
    float4 v = *reinterpret_cast<const float4*>(x + (size_t)idx * 4);
    union { __half2 h[2]; uint2 u; } pk;
    pk.h[0] = __floats2half2_rn(v.x, v.y);
    pk.h[1] = __floats2half2_rn(v.z, v.w);
    *reinterpret_cast<uint2*>(xh + (size_t)idx * 4) = pk.u;
}

// adj fp32 -> fp16 copy + per-row sums. One warp per adjacency row.
__global__ __launch_bounds__(256) void conv_rowsum(
    const float* __restrict__ adj, __half* __restrict__ adjh, float* __restrict__ rs)
{
    int warp = (blockIdx.x * blockDim.x + threadIdx.x) >> 5;   // row id
    int lane = threadIdx.x & 31;
    const float* src = adj + (size_t)warp * NN;
    __half* dst = adjh + (size_t)warp * NN;
    float s = 0.f;
#pragma unroll
    for (int i = 0; i < 8; i++) {
        float4 v = *reinterpret_cast<const float4*>(src + i * 128 + lane * 4);
        s += v.x + v.y + v.z + v.w;
        union { __half2 h[2]; uint2 u; } pk;
        pk.h[0] = __floats2half2_rn(v.x, v.y);
        pk.h[1] = __floats2half2_rn(v.z, v.w);
        *reinterpret_cast<uint2*>(dst + i * 128 + lane * 4) = pk.u;
    }
#pragma unroll
    for (int off = 16; off; off >>= 1) s += __shfl_xor_sync(0xFFFFFFFFu, s, off);
    if (lane == 0) rs[warp] = s;
}

// ============================================================================
// Shared fragment-map helpers (proven in adj_layer)
// ============================================================================
struct FragMap {
    uint32_t Qa[4];
    uint32_t Qb[2];
    int m_warp, n_warp, g, tg;
};

__device__ __forceinline__ FragMap make_fragmap(int tid, int nwarp_span /*32 or 16*/) {
    FragMap f;
    const int wid = tid >> 5;
    const int lid = tid & 31;
    f.g  = lid >> 2;
    f.tg = lid & 3;
    f.m_warp = (wid & 1) * 64;
    f.n_warp = (wid >> 1) * nwarp_span;
    const int xr  = lid & 7;
    const int rAo = ((lid >> 3) & 1) * 8;
    const int w0A = (lid >> 4) & 1;
#pragma unroll
    for (int mt = 0; mt < 4; mt++) {
        int r = f.m_warp + mt * 16 + rAo + xr;
        f.Qa[mt] = (uint32_t)(r * 128 + ((w0A ^ xr) << 4));
    }
    const int w0B = (lid >> 3) & 1;
    const int ntB = (lid >> 4) & 1;
#pragma unroll
    for (int p = 0; p < 2; p++) {
        int rn = f.n_warp + (p * 2 + ntB) * 8 + xr;
        f.Qb[p] = (uint32_t)(rn * 128 + ((w0B ^ xr) << 4));
    }
    return f;
}

// ============================================================================
// Embed: hT0 = (x @ Wemb)^T * SH   (fp16 MMA, single K=64 chunk)
// ============================================================================
#define ETILE 16384
#define HBUF_STRIDE 136
#define EHBUF_OFF (2 * ETILE)
#define SMTOT_E (EHBUF_OFF + 128 * HBUF_STRIDE * 2)    // 67584

__global__ __launch_bounds__(256, 2) void embed_mma(
    const __half* __restrict__ xh, const __half* __restrict__ wembT,
    __half* __restrict__ hTout)
{
    extern __shared__ __align__(1024) char smem[];
    const uint32_t sb = smem_u32(smem);
    const int tid = threadIdx.x;
    const int row0 = blockIdx.x * 128;
    const int b = row0 >> 10;
    const int node0 = row0 & (NN - 1);

    FragMap f = make_fragmap(tid, 32);

    load_tile16(sb,         xh + (size_t)row0 * IN_DIM, IN_DIM, tid);
    load_tile16(sb + ETILE, wembT, IN_DIM, tid);
    CP_COMMIT();

    float acc[4][4][4];
#pragma unroll
    for (int mt = 0; mt < 4; mt++)
#pragma unroll
        for (int nt = 0; nt < 4; nt++)
#pragma unroll
            for (int r = 0; r < 4; r++) acc[mt][nt][r] = 0.f;

    CP_WAIT0();
    __syncthreads();

#pragma unroll
    for (int kk = 0; kk < 4; kk++) {
        const uint32_t kx = (uint32_t)kk << 5;
        uint32_t bf[4][2];
        LDMX4(bf[0][0], bf[0][1], bf[1][0], bf[1][1], (sb + ETILE + f.Qb[0]) ^ kx);
        LDMX4(bf[2][0], bf[2][1], bf[3][0], bf[3][1], (sb + ETILE + f.Qb[1]) ^ kx);
#pragma unroll
        for (int mt = 0; mt < 4; mt++) {
            uint32_t a0, a1, a2, a3;
            LDMX4(a0, a1, a2, a3, (sb + f.Qa[mt]) ^ kx);
#pragma unroll
            for (int nt = 0; nt < 4; nt++)
                mma_f16(acc[mt][nt], a0, a1, a2, a3, bf[nt][0], bf[nt][1]);
        }
    }

    // transpose via hbuf, scaled by SH
    __half* hb = reinterpret_cast<__half*>(smem + EHBUF_OFF);
#pragma unroll
    for (int mt = 0; mt < 4; mt++) {
        int mr = f.m_warp + mt * 16 + f.g;
#pragma unroll
        for (int nt = 0; nt < 4; nt++) {
            int col = f.n_warp + nt * 8 + 2 * f.tg;
            hb[(col)     * HBUF_STRIDE + mr]     = __float2half(acc[mt][nt][0] * SH_F);
            hb[(col + 1) * HBUF_STRIDE + mr]     = __float2half(acc[mt][nt][1] * SH_F);
            hb[(col)     * HBUF_STRIDE + mr + 8] = __float2half(acc[mt][nt][2] * SH_F);
            hb[(col + 1) * HBUF_STRIDE + mr + 8] = __float2half(acc[mt][nt][3] * SH_F);
        }
    }
    __syncthreads();
#pragma unroll
    for (int p = 0; p < 8; p++) {
        int idx = tid + p * 256;
        int c = idx >> 4, u = idx & 15;
        uint4 v = *reinterpret_cast<const uint4*>(hb + c * HBUF_STRIDE + u * 8);
        *reinterpret_cast<uint4*>(
            hTout + ((size_t)(b * HID + c)) * NN + node0 + u * 8) = v;
    }
}

// ============================================================================
// Proj: out = (h3 @ Wproj + bproj) * mask   (fp16 MMA, K=128 in 2 chunks)
// h3h is [node][128] fp16 scaled by SP. Warp tile 64x16 (2x4 grid over N=64).
// ============================================================================
#define SMTOT_P (2 * ETILE + 2 * 8192)     // 49152

__global__ __launch_bounds__(256, 2) void proj_mma(
    const __half* __restrict__ h3h, const __half* __restrict__ wpT,
    const float* __restrict__ bproj, const float* __restrict__ mask,
    float* __restrict__ out)
{
    extern __shared__ __align__(1024) char smem[];
    const uint32_t sb = smem_u32(smem);
    const int tid = threadIdx.x;
    const int row0 = blockIdx.x * 128;

    FragMap f = make_fragmap(tid, 16);     // n_warp in {0,16,32,48}

    load_tile16(sb,          h3h + (size_t)row0 * HID,      HID, tid);
    load_tile16(sb + ETILE,  h3h + (size_t)row0 * HID + 64, HID, tid);
    load_tile8 (sb + 2 * ETILE,        wpT,           64, tid);
    load_tile8 (sb + 2 * ETILE + 8192, wpT + OUTD * 64, 64, tid);
    CP_COMMIT();

    float acc[4][2][4];
#pragma unroll
    for (int mt = 0; mt < 4; mt++)
#pragma unroll
        for (int nt = 0; nt < 2; nt++)
#pragma unroll
            for (int r = 0; r < 4; r++) acc[mt][nt][r] = 0.f;

    CP_WAIT0();
    __syncthreads();

#pragma unroll
    for (int ch = 0; ch < 2; ch++) {
        const uint32_t sA = sb + ch * ETILE;
        const uint32_t sW = sb + 2 * ETILE + ch * 8192;
#pragma unroll
        for (int kk = 0; kk < 4; kk++) {
            const uint32_t kx = (uint32_t)kk << 5;
            uint32_t bf[2][2];
            LDMX4(bf[0][0], bf[0][1], bf[1][0], bf[1][1], (sW + f.Qb[0]) ^ kx);
#pragma unroll
            for (int mt = 0; mt < 4; mt++) {
                uint32_t a0, a1, a2, a3;
                LDMX4(a0, a1, a2, a3, (sA + f.Qa[mt]) ^ kx);
#pragma unroll
                for (int nt = 0; nt < 2; nt++)
                    mma_f16(acc[mt][nt], a0, a1, a2, a3, bf[nt][0], bf[nt][1]);
            }
        }
    }

    // epilogue: *16384 + bproj, *mask, fp32 store
#pragma unroll
    for (int mt = 0; mt < 4; mt++) {
        int mr = row0 + f.m_warp + mt * 16 + f.g;
        float m0 = mask[mr], m1 = mask[mr + 8];
#pragma unroll
        for (int nt = 0; nt < 2; nt++) {
            int col = f.n_warp + nt * 8 + 2 * f.tg;
            float b0 = bproj[col], b1 = bproj[col + 1];
            float2 p0, p1;
            p0.x = fmaf(acc[mt][nt][0], UNSC2_F, b0) * m0;
            p0.y = fmaf(acc[mt][nt][1], UNSC2_F, b1) * m0;
            p1.x = fmaf(acc[mt][nt][2], UNSC2_F, b0) * m1;
            p1.y = fmaf(acc[mt][nt][3], UNSC2_F, b1) * m1;
            *reinterpret_cast<float2*>(&out[(size_t)mr * OUTD + col])       = p0;
            *reinterpret_cast<float2*>(&out[(size_t)(mr + 8) * OUTD + col]) = p1;
        }
    }
}

// ============================================================================
// Fused GCN layer (unchanged R11 mainloop):
//   acc = adjh[b] @ (h_in*SH)^T ; Tbuf = acc/64 ; h' = relu(1024*(Tbuf@Wl)+rs*bl)
//   LAST=false: store (h'*SH)^T fp16 ; LAST=true: store h'*SP fp16 NORMAL layout
// ============================================================================
#define ST 3
#define BKH 64
#define NITH (NN / BKH)            // 16
#define TILE16 16384
#define HBUF_OFF (4 * TILE16)
#define SMTOT (HBUF_OFF + 128 * HBUF_STRIDE * 2)   // 100352 B

template<bool LAST>
__global__ __launch_bounds__(256, 2) void adj_layer(
    const __half* __restrict__ adjh, const __half* __restrict__ hTin,
    const __half* __restrict__ wlt,  const float* __restrict__ bl,
    const float* __restrict__ rowsum,
    __half* __restrict__ hTout, __half* __restrict__ h3out)
{
    extern __shared__ __align__(1024) char smem[];
    const uint32_t sb = smem_u32(smem);
    const int tid = threadIdx.x;
    const int b    = blockIdx.y;
    const int row0 = blockIdx.x * 128;

    FragMap f = make_fragmap(tid, 32);
    const int m_warp = f.m_warp, n_warp = f.n_warp, g = f.g, tg = f.tg;

    const __half* Ab = adjh + (size_t)b * NN * NN + (size_t)row0 * NN;
    const __half* Bb = hTin + (size_t)b * HID * NN;

    float acc[4][4][4];
#pragma unroll
    for (int mt = 0; mt < 4; mt++)
#pragma unroll
        for (int nt = 0; nt < 4; nt++)
#pragma unroll
            for (int r = 0; r < 4; r++) acc[mt][nt][r] = 0.f;

#pragma unroll
    for (int p = 0; p < 2; p++) {
        load_tile16(sb + p * TILE16, Ab + p * BKH, NN, tid);
        load_tile16(sb + (ST + p) * TILE16, Bb + p * BKH, NN, tid);
        CP_COMMIT();
    }

    for (int it = 0; it < NITH; it++) {
        const int s = it % ST;
        CP_WAIT1();
        __syncthreads();

        const uint32_t sA = sb + s * TILE16;
        const uint32_t sB = sb + (ST + s) * TILE16;

        uint32_t bf[2][4][2];
        uint32_t af[2][4];
        LDMX4(bf[0][0][0], bf[0][0][1], bf[0][1][0], bf[0][1][1], sB + f.Qb[0]);
        LDMX4(bf[0][2][0], bf[0][2][1], bf[0][3][0], bf[0][3][1], sB + f.Qb[1]);
        LDMX4(af[0][0], af[0][1], af[0][2], af[0][3], sA + f.Qa[0]);

#pragma unroll
        for (int kk = 0; kk < 4; kk++) {
            const uint32_t kx  = (uint32_t)kk << 5;
            const uint32_t kxn = (uint32_t)(kk + 1) << 5;
            const int cb = kk & 1, nb = cb ^ 1;
            if (kk < 3) {
                LDMX4(bf[nb][0][0], bf[nb][0][1], bf[nb][1][0], bf[nb][1][1],
                      (sB + f.Qb[0]) ^ kxn);
                LDMX4(bf[nb][2][0], bf[nb][2][1], bf[nb][3][0], bf[nb][3][1],
                      (sB + f.Qb[1]) ^ kxn);
            }
#pragma unroll
            for (int mt = 0; mt < 4; mt++) {
                const int ca = mt & 1, na = ca ^ 1;
                if (mt < 3) {
                    LDMX4(af[na][0], af[na][1], af[na][2], af[na][3],
                          (sA + f.Qa[mt + 1]) ^ kx);
                } else if (kk < 3) {
                    LDMX4(af[na][0], af[na][1], af[na][2], af[na][3],
                          (sA + f.Qa[0]) ^ kxn);
                }
#pragma unroll
                for (int nt = 0; nt < 4; nt++)
                    mma_f16(acc[mt][nt], af[ca][0], af[ca][1], af[ca][2], af[ca][3],
                            bf[cb][nt][0], bf[cb][nt][1]);
            }
            if (kk == 0) {
                if (it + 2 < NITH) {
                    const int sl = (it + 2) % ST;
                    load_tile16(sb + sl * TILE16, Ab + (it + 2) * BKH, NN, tid);
                    load_tile16(sb + (ST + sl) * TILE16, Bb + (it + 2) * BKH, NN, tid);
                }
                CP_COMMIT();
            }
        }
    }

    // ---- epilogue ----
    load_tile16(sb + 2 * TILE16, wlt, HID, tid);
    CP_COMMIT();
    __syncthreads();
    load_tile16(sb + 3 * TILE16, wlt + 64, HID, tid);
    CP_COMMIT();

    {
        char* tb = smem + (n_warp >> 6) * TILE16;
        const int lpb = (n_warp & 63) >> 1;
#pragma unroll
        for (int mt = 0; mt < 4; mt++) {
            int mr = m_warp + mt * 16 + g;
#pragma unroll
            for (int nt = 0; nt < 4; nt++) {
                int lp = lpb + nt * 4 + tg;
                int w = lp >> 2, inner = (lp & 3) * 4;
                *reinterpret_cast<uint32_t*>(
                    tb + mr * 128 + (((w ^ (mr & 7))) << 4) + inner) =
                    pack_h2(acc[mt][nt][0] * ST2_F, acc[mt][nt][1] * ST2_F);
                *reinterpret_cast<uint32_t*>(
                    tb + (mr + 8) * 128 + (((w ^ ((mr + 8) & 7))) << 4) + inner) =
                    pack_h2(acc[mt][nt][2] * ST2_F, acc[mt][nt][3] * ST2_F);
            }
        }
    }
    CP_WAIT0();
    __syncthreads();

    float acc2[4][4][4];
#pragma unroll
    for (int mt = 0; mt < 4; mt++)
#pragma unroll
        for (int nt = 0; nt < 4; nt++)
#pragma unroll
            for (int r = 0; r < 4; r++) acc2[mt][nt][r] = 0.f;

#pragma unroll
    for (int ch = 0; ch < 2; ch++) {
        const uint32_t sT = sb + ch * TILE16;
        const uint32_t sW = sb + (2 + ch) * TILE16;
#pragma unroll
        for (int kk = 0; kk < 4; kk++) {
            const uint32_t kx = (uint32_t)kk << 5;
            uint32_t bf2[4][2];
            LDMX4(bf2[0][0], bf2[0][1], bf2[1][0], bf2[1][1], (sW + f.Qb[0]) ^ kx);
            LDMX4(bf2[2][0], bf2[2][1], bf2[3][0], bf2[3][1], (sW + f.Qb[1]) ^ kx);
#pragma unroll
            for (int mt = 0; mt < 4; mt++) {
                uint32_t a0, a1, a2, a3;
                LDMX4(a0, a1, a2, a3, (sT + f.Qa[mt]) ^ kx);
#pragma unroll
                for (int nt = 0; nt < 4; nt++)
                    mma_f16(acc2[mt][nt], a0, a1, a2, a3, bf2[nt][0], bf2[nt][1]);
            }
        }
    }

    const float* rsb = rowsum + b * NN + row0;
    float rlo[4], rhi[4];
#pragma unroll
    for (int mt = 0; mt < 4; mt++) {
        rlo[mt] = rsb[m_warp + mt * 16 + g];
        rhi[mt] = rsb[m_warp + mt * 16 + g + 8];
    }
    float b0v[4], b1v[4];
#pragma unroll
    for (int nt = 0; nt < 4; nt++) {
        int col = n_warp + nt * 8 + 2 * tg;
        b0v[nt] = bl[col];
        b1v[nt] = bl[col + 1];
    }

    __half* hb = reinterpret_cast<__half*>(smem + HBUF_OFF);

#pragma unroll
    for (int mt = 0; mt < 4; mt++) {
        int mr = m_warp + mt * 16 + g;
#pragma unroll
        for (int nt = 0; nt < 4; nt++) {
            int col = n_warp + nt * 8 + 2 * tg;
            float v00 = fmaxf(fmaf(acc2[mt][nt][0], UNSC_F, rlo[mt] * b0v[nt]), 0.f);
            float v01 = fmaxf(fmaf(acc2[mt][nt][1], UNSC_F, rlo[mt] * b1v[nt]), 0.f);
            float v10 = fmaxf(fmaf(acc2[mt][nt][2], UNSC_F, rhi[mt] * b0v[nt]), 0.f);
            float v11 = fmaxf(fmaf(acc2[mt][nt][3], UNSC_F, rhi[mt] * b1v[nt]), 0.f);
            if (LAST) {
                // normal-layout fp16, scaled SP=2^-14 (proj input; overflow-safe)
                *reinterpret_cast<uint32_t*>(
                    &h3out[(size_t)(b * NN + row0 + mr) * HID + col]) =
                    pack_h2(v00 * SP_F, v01 * SP_F);
                *reinterpret_cast<uint32_t*>(
                    &h3out[(size_t)(b * NN + row0 + mr + 8) * HID + col]) =
                    pack_h2(v10 * SP_F, v11 * SP_F);
            } else {
                hb[(col)     * HBUF_STRIDE + mr]     = __float2half(v00 * SH_F);
                hb[(col + 1) * HBUF_STRIDE + mr]     = __float2half(v01 * SH_F);
                hb[(col)     * HBUF_STRIDE + mr + 8] = __float2half(v10 * SH_F);
                hb[(col + 1) * HBUF_STRIDE + mr + 8] = __float2half(v11 * SH_F);
            }
        }
    }

    if (!LAST) {
        __syncthreads();
#pragma unroll
        for (int p = 0; p < 8; p++) {
            int idx = tid + p * 256;
            int c = idx >> 4, u = idx & 15;
            uint4 v = *reinterpret_cast<const uint4*>(hb + c * HBUF_STRIDE + u * 8);
            *reinterpret_cast<uint4*>(
                hTout + ((size_t)(b * HID + c)) * NN + row0 + u * 8) = v;
        }
    }
}

// ============================================================================
// Launch
// Inputs: 0 node_features [B,N,64] | 1 adjacency [B,N,N] | 2 node_mask [B,N,1]
//         3 W_embed [64,128] | 4 Wl [3,128,128] | 5 bl [3,128]
//         6 W_proj [128,64]  | 7 b_proj [64]      Output: [B,N,64] f32
// ============================================================================
extern "C" void kernel_launch(void* const* d_in, const int* in_sizes, int n_in,
                              void* d_out, int out_size)
{
    const float* x     = (const float*)d_in[0];
    const float* adj   = (const float*)d_in[1];
    const float* mask  = (const float*)d_in[2];
    const float* Wemb  = (const float*)d_in[3];
    const float* Wl    = (const float*)d_in[4];
    const float* bl    = (const float*)d_in[5];
    const float* Wproj = (const float*)d_in[6];
    const float* bproj = (const float*)d_in[7];
    float* out = (float*)d_out;

    __half *adjh = nullptr, *hT = nullptr, *wlt = nullptr;
    __half *xh = nullptr, *wembT = nullptr, *wpT = nullptr;
    float *rs = nullptr;
    cudaGetSymbolAddress((void**)&adjh,  g_adjh);
    cudaGetSymbolAddress((void**)&hT,    g_hT);
    cudaGetSymbolAddress((void**)&wlt,   g_WlTh);
    cudaGetSymbolAddress((void**)&xh,    g_xh);
    cudaGetSymbolAddress((void**)&wembT, g_WembTh);
    cudaGetSymbolAddress((void**)&wpT,   g_WprojTh);
    cudaGetSymbolAddress((void**)&rs,    g_rowsum);
    __half* hT0 = hT;
    __half* hT1 = hT + (size_t)BB * HID * NN;
    __half* h3h = hT1;                      // layer-2 input buffer reused for h3

    cudaFuncSetAttribute(adj_layer<false>,
                         cudaFuncAttributeMaxDynamicSharedMemorySize, SMTOT);
    cudaFuncSetAttribute(adj_layer<true>,
                         cudaFuncAttributeMaxDynamicSharedMemorySize, SMTOT);
    cudaFuncSetAttribute(embed_mma,
                         cudaFuncAttributeMaxDynamicSharedMemorySize, SMTOT_E);
    cudaFuncSetAttribute(proj_mma,
                         cudaFuncAttributeMaxDynamicSharedMemorySize, SMTOT_P);

    // prep + conversions
    prep_weights<<<NUM_LAYERS + 2, 256>>>(Wl, Wemb, Wproj, wlt, wembT, wpT);
    conv_x<<<(BB * NN * IN_DIM) / (4 * 256), 256>>>(x, xh);
    embed_mma<<<BB * NN / 128, 256, SMTOT_E>>>(xh, wembT, hT0);
    conv_rowsum<<<BB * NN / 8, 256>>>(adj, adjh, rs);

    dim3 bigg(NN / 128, BB);   // (8, 32)
    adj_layer<false><<<bigg, 256, SMTOT>>>(adjh, hT0, wlt,                 bl,
                                           rs, hT1, nullptr);
    adj_layer<false><<<bigg, 256, SMTOT>>>(adjh, hT1, wlt + HID * HID,     bl + HID,
                                           rs, hT0, nullptr);
    adj_layer<true ><<<bigg, 256, SMTOT>>>(adjh, hT0, wlt + 2 * HID * HID, bl + 2 * HID,
                                           rs, nullptr, h3h);

    // projection + mask (fp16 MMA)
    proj_mma<<<BB * NN / 128, 256, SMTOT_P>>>(h3h, wpT, bproj, mask, out);
}